// round 4
// baseline (speedup 1.0000x reference)
#include <cuda_runtime.h>

#define NUc 100000
#define NIc 50000
#define NVc 150000   // NUc + NIc
#define Dc  64
#define NEc 1000000

typedef unsigned long long ull;

// ---------------- scratch ------------------------------------------------
__device__ float g_all[(size_t)NVc * Dc];  // current embeddings (concat u,i)
__device__ float g_acc[(size_t)NVc * Dc];  // running sum for final mean
__device__ float g_X1 [(size_t)NVc * Dc];  // X * D^-1/2 (input to gather)
__device__ float g_E  [(size_t)NVc * Dc];  // hyperedge embs, pre-scaled by De^-1
__device__ int   g_deg[NVc];
__device__ float g_isq[NVc];               // deg^-1/2 (0 if deg==0)
__device__ float g_inv[NVc];               // deg^-1   (0 if deg==0)
__device__ int   g_off[NVc];               // CSR row offsets
__device__ int   g_cur[NVc];               // fill cursors
__device__ int   g_adj[NEc * 2];           // neighbor lists (opposite node id)
__device__ int   g_bsum[256];              // scan partials

// ---------------- f32x2 helpers -----------------------------------------
__device__ __forceinline__ ull ffma2(ull a, ull b, ull c) {
    ull d;
    asm("fma.rn.f32x2 %0, %1, %2, %3;" : "=l"(d) : "l"(a), "l"(b), "l"(c));
    return d;
}
__device__ __forceinline__ void unpack2(ull v, float& lo, float& hi) {
    asm("mov.b64 {%0,%1}, %2;" : "=f"(lo), "=f"(hi) : "l"(v));
}

// ---------------- degree / normalization --------------------------------

__global__ void k_zero_deg() {
    int i = blockIdx.x * blockDim.x + threadIdx.x;
    if (i < NVc) g_deg[i] = 0;
}

__global__ void k_count(const int* __restrict__ eu, const int* __restrict__ ei) {
    int e = blockIdx.x * blockDim.x + threadIdx.x;
    if (e < NEc) {
        atomicAdd(&g_deg[eu[e]], 1);
        atomicAdd(&g_deg[NUc + ei[e]], 1);
    }
}

__global__ void k_norm() {
    int n = blockIdx.x * blockDim.x + threadIdx.x;
    if (n < NVc) {
        int d = g_deg[n];
        if (d > 0) {
            float fd = (float)d;
            g_isq[n] = rsqrtf(fd);
            g_inv[n] = 1.0f / fd;
        } else {
            g_isq[n] = 0.0f;
            g_inv[n] = 0.0f;
        }
    }
}

// ---------------- exclusive scan of g_deg -> g_off -----------------------

__global__ void k_scan1() {
    __shared__ int s[1024];
    int i = blockIdx.x * 1024 + threadIdx.x;
    int v = (i < NVc) ? g_deg[i] : 0;
    s[threadIdx.x] = v;
    __syncthreads();
    #pragma unroll
    for (int d = 1; d < 1024; d <<= 1) {
        int t = (threadIdx.x >= d) ? s[threadIdx.x - d] : 0;
        __syncthreads();
        s[threadIdx.x] += t;
        __syncthreads();
    }
    if (i < NVc) g_off[i] = s[threadIdx.x] - v;
    if (threadIdx.x == 1023) g_bsum[blockIdx.x] = s[1023];
}

__global__ void k_scan2(int nblocks) {
    __shared__ int s[256];
    int v = (threadIdx.x < nblocks) ? g_bsum[threadIdx.x] : 0;
    s[threadIdx.x] = v;
    __syncthreads();
    #pragma unroll
    for (int d = 1; d < 256; d <<= 1) {
        int t = (threadIdx.x >= d) ? s[threadIdx.x - d] : 0;
        __syncthreads();
        s[threadIdx.x] += t;
        __syncthreads();
    }
    g_bsum[threadIdx.x] = s[threadIdx.x] - v;
}

__global__ void k_scan3() {
    int i = blockIdx.x * blockDim.x + threadIdx.x;
    if (i < NVc) {
        int o = g_off[i] + g_bsum[i >> 10];
        g_off[i] = o;
        g_cur[i] = o;
    }
}

__global__ void k_fill(const int* __restrict__ eu, const int* __restrict__ ei) {
    int e = blockIdx.x * blockDim.x + threadIdx.x;
    if (e < NEc) {
        int u = eu[e];
        int it = NUc + ei[e];
        int pu = atomicAdd(&g_cur[u], 1);
        g_adj[pu] = it;
        int pi = atomicAdd(&g_cur[it], 1);
        g_adj[pi] = u;
    }
}

// ---------------- embedding init -----------------------------------------

__global__ void k_init(const float4* __restrict__ u4, const float4* __restrict__ i4) {
    int idx = blockIdx.x * blockDim.x + threadIdx.x;
    if (idx < NVc * (Dc / 4)) {
        float4 v = (idx < NUc * (Dc / 4)) ? u4[idx] : i4[idx - NUc * (Dc / 4)];
        ((float4*)g_all)[idx] = v;
        ((float4*)g_acc)[idx] = v;
        int n = idx >> 4;
        float s = g_isq[n];
        ((float4*)g_X1)[idx] = make_float4(v.x * s, v.y * s, v.z * s, v.w * s);
    }
}

// ---------------- gather 1: E'[n] = inv[n] * sum X1[opp] -----------------
// warp per node; half-warp split over neighbors, float4 over columns

__global__ void __launch_bounds__(256) k_gatherE() {
    int lane = threadIdx.x & 31;
    int w    = threadIdx.x >> 5;
    int n = blockIdx.x * 8 + w;
    if (n >= NVc) return;

    int c    = lane & 15;
    int half = lane >> 4;
    int deg  = g_deg[n];
    const int* __restrict__ adj = g_adj + g_off[n];
    const float4* __restrict__ X = (const float4*)g_X1;

    float4 acc = make_float4(0.f, 0.f, 0.f, 0.f);
    int j = half;
    for (; j + 2 < deg; j += 4) {
        int o0 = adj[j], o1 = adj[j + 2];
        float4 v0 = X[o0 * 16 + c];
        float4 v1 = X[o1 * 16 + c];
        acc.x += v0.x + v1.x; acc.y += v0.y + v1.y;
        acc.z += v0.z + v1.z; acc.w += v0.w + v1.w;
    }
    for (; j < deg; j += 2) {
        float4 v = X[adj[j] * 16 + c];
        acc.x += v.x; acc.y += v.y; acc.z += v.z; acc.w += v.w;
    }
    acc.x += __shfl_xor_sync(0xffffffffu, acc.x, 16);
    acc.y += __shfl_xor_sync(0xffffffffu, acc.y, 16);
    acc.z += __shfl_xor_sync(0xffffffffu, acc.z, 16);
    acc.w += __shfl_xor_sync(0xffffffffu, acc.w, 16);

    if (half == 0) {
        float inv = g_inv[n];
        ((float4*)g_E)[n * 16 + c] =
            make_float4(acc.x * inv, acc.y * inv, acc.z * inv, acc.w * inv);
    }
}

// ---------------- fused: gather2 + GEMVs + lrelu + L2norm ----------------
// 4 nodes per warp; FFMA2-packed dual GEMV; weights reused across 4 nodes.

extern __shared__ float4 dynsmem[];

__global__ void __launch_bounds__(256) k_layer(const float* __restrict__ Wgc,
                                               const float* __restrict__ bgc,
                                               const float* __restrict__ Wbi,
                                               const float* __restrict__ bbi,
                                               float* __restrict__ out) {
    float4* sW4 = dynsmem;            // [k*32 + j] = {Wg[j][k], Wg[j+32][k], Wb[j][k], Wb[j+32][k]}
    float4* sGM = dynsmem + 2048;     // [warp*256 + nd*64 + k] = {g,g,m,m}
    __shared__ float sbg[64], sbb[64];

    for (int idx = threadIdx.x; idx < 2048; idx += 256) {
        int k = idx >> 5, j = idx & 31;
        sW4[idx] = make_float4(Wgc[j * 64 + k], Wgc[(j + 32) * 64 + k],
                               Wbi[j * 64 + k], Wbi[(j + 32) * 64 + k]);
    }
    if (threadIdx.x < 64) {
        sbg[threadIdx.x] = bgc[threadIdx.x];
        sbb[threadIdx.x] = bbi[threadIdx.x];
    }
    __syncthreads();

    int lane = threadIdx.x & 31;
    int w    = threadIdx.x >> 5;
    int c    = lane & 15;
    int half = lane >> 4;
    float4* myGM = sGM + w * 256;

    for (int base = blockIdx.x * 32 + w * 4; base < NVc; base += gridDim.x * 32) {
        __syncwarp();
        float isqs[4];

        // ---- phase 1: gather Y for 4 nodes, stage {g,g,m,m} ----
        #pragma unroll
        for (int nd = 0; nd < 4; nd++) {
            int n = base + nd;                  // NVc % 4 == 0, base % 4 == 0 -> always valid
            int deg = g_deg[n];
            const int* __restrict__ adj = g_adj + g_off[n];
            const float4* __restrict__ E4 = (const float4*)g_E;

            float4 acc = make_float4(0.f, 0.f, 0.f, 0.f);
            int j = half;
            for (; j + 2 < deg; j += 4) {
                int o0 = adj[j], o1 = adj[j + 2];
                float4 v0 = E4[o0 * 16 + c];
                float4 v1 = E4[o1 * 16 + c];
                acc.x += v0.x + v1.x; acc.y += v0.y + v1.y;
                acc.z += v0.z + v1.z; acc.w += v0.w + v1.w;
            }
            for (; j < deg; j += 2) {
                float4 v = E4[adj[j] * 16 + c];
                acc.x += v.x; acc.y += v.y; acc.z += v.z; acc.w += v.w;
            }
            acc.x += __shfl_xor_sync(0xffffffffu, acc.x, 16);
            acc.y += __shfl_xor_sync(0xffffffffu, acc.y, 16);
            acc.z += __shfl_xor_sync(0xffffffffu, acc.z, 16);
            acc.w += __shfl_xor_sync(0xffffffffu, acc.w, 16);

            float isq = g_isq[n];
            isqs[nd] = isq;
            if (half == 0) {
                float4 x4 = ((const float4*)g_all)[n * 16 + c];
                float gx = acc.x * isq, gy = acc.y * isq, gz = acc.z * isq, gw = acc.w * isq;
                myGM[nd * 64 + 4 * c + 0] = make_float4(gx, gx, x4.x * gx, x4.x * gx);
                myGM[nd * 64 + 4 * c + 1] = make_float4(gy, gy, x4.y * gy, x4.y * gy);
                myGM[nd * 64 + 4 * c + 2] = make_float4(gz, gz, x4.z * gz, x4.z * gz);
                myGM[nd * 64 + 4 * c + 3] = make_float4(gw, gw, x4.w * gw, x4.w * gw);
            }
        }
        __syncwarp();

        // ---- phase 2: dual GEMV for 4 nodes, packed f32x2 ----
        ull A[4] = {0, 0, 0, 0};
        ull B[4] = {0, 0, 0, 0};
        const ulonglong2* __restrict__ pW = (const ulonglong2*)sW4;
        const ulonglong2* __restrict__ pG = (const ulonglong2*)myGM;
        #pragma unroll 8
        for (int k = 0; k < 64; k++) {
            ulonglong2 wp = pW[k * 32 + lane];     // .x = {wg_j, wg_j32}, .y = {wb_j, wb_j32}
            ulonglong2 q0 = pG[k];
            ulonglong2 q1 = pG[64 + k];
            ulonglong2 q2 = pG[128 + k];
            ulonglong2 q3 = pG[192 + k];
            A[0] = ffma2(wp.x, q0.x, A[0]);  B[0] = ffma2(wp.y, q0.y, B[0]);
            A[1] = ffma2(wp.x, q1.x, A[1]);  B[1] = ffma2(wp.y, q1.y, B[1]);
            A[2] = ffma2(wp.x, q2.x, A[2]);  B[2] = ffma2(wp.y, q2.y, B[2]);
            A[3] = ffma2(wp.x, q3.x, A[3]);  B[3] = ffma2(wp.y, q3.y, B[3]);
        }

        // ---- phase 3: epilogue per node ----
        #pragma unroll
        for (int nd = 0; nd < 4; nd++) {
            int n = base + nd;
            float a0, a1, b0, b1;
            unpack2(A[nd], a0, a1);
            unpack2(B[nd], b0, b1);

            float x0 = g_all[n * 64 + lane];
            float x1 = g_all[n * 64 + 32 + lane];

            float h0 = a0 + sbg[lane]      + x0; h0 = h0 > 0.f ? h0 : 0.2f * h0;
            float h1 = a1 + sbg[lane + 32] + x1; h1 = h1 > 0.f ? h1 : 0.2f * h1;
            float p0 = b0 + sbb[lane];           p0 = p0 > 0.f ? p0 : 0.2f * p0;
            float p1 = b1 + sbb[lane + 32];      p1 = p1 > 0.f ? p1 : 0.2f * p1;

            float n0 = h0 + p0, n1 = h1 + p1;
            float s = n0 * n0 + n1 * n1;
            #pragma unroll
            for (int o = 16; o; o >>= 1) s += __shfl_xor_sync(0xffffffffu, s, o);
            float invn = 1.0f / fmaxf(sqrtf(s), 1e-12f);
            n0 *= invn; n1 *= invn;

            if (out) {
                out[n * 64 + lane]      = (g_acc[n * 64 + lane]      + n0) * 0.25f;
                out[n * 64 + 32 + lane] = (g_acc[n * 64 + 32 + lane] + n1) * 0.25f;
            } else {
                float isq = isqs[nd];
                g_all[n * 64 + lane]       = n0;
                g_all[n * 64 + 32 + lane]  = n1;
                g_acc[n * 64 + lane]      += n0;
                g_acc[n * 64 + 32 + lane] += n1;
                g_X1[n * 64 + lane]        = n0 * isq;
                g_X1[n * 64 + 32 + lane]   = n1 * isq;
            }
        }
    }
}

// ---------------- launch --------------------------------------------------

extern "C" void kernel_launch(void* const* d_in, const int* in_sizes, int n_in,
                              void* d_out, int out_size) {
    const float* u_emb = (const float*)d_in[0];
    const float* i_emb = (const float*)d_in[1];
    const float* Wgc   = (const float*)d_in[2];
    const float* bgc   = (const float*)d_in[3];
    const float* Wbi   = (const float*)d_in[4];
    const float* bbi   = (const float*)d_in[5];
    const int*   eu    = (const int*)d_in[6];
    const int*   ei    = (const int*)d_in[7];
    float* out = (float*)d_out;

    const int nodeVecBlocks  = (NVc * (Dc / 4) + 255) / 256;  // 9375
    const int nodeBlocks     = (NVc + 255) / 256;             // 586
    const int edgeBlocks     = (NEc + 255) / 256;             // 3907
    const int scanBlocks     = (NVc + 1023) / 1024;           // 147
    const int warpNodeBlocks = (NVc + 7) / 8;                 // 18750
    const int layerSmem      = 4096 * (int)sizeof(float4);    // 64 KB

    static int smem_set = 0;
    if (!smem_set) {
        cudaFuncSetAttribute(k_layer, cudaFuncAttributeMaxDynamicSharedMemorySize, layerSmem);
        smem_set = 1;
    }

    k_zero_deg<<<nodeBlocks, 256>>>();
    k_count<<<edgeBlocks, 256>>>(eu, ei);
    k_norm<<<nodeBlocks, 256>>>();
    k_scan1<<<scanBlocks, 1024>>>();
    k_scan2<<<1, 256>>>(scanBlocks);
    k_scan3<<<nodeBlocks, 256>>>();
    k_fill<<<edgeBlocks, 256>>>(eu, ei);
    k_init<<<nodeVecBlocks, 256>>>((const float4*)u_emb, (const float4*)i_emb);

    for (int l = 0; l < 3; l++) {
        k_gatherE<<<warpNodeBlocks, 256>>>();
        k_layer<<<1184, 256, layerSmem>>>(Wgc + l * 4096, bgc + l * 64,
                                          Wbi + l * 4096, bbi + l * 64,
                                          (l == 2) ? out : (float*)0);
    }
}